// round 2
// baseline (speedup 1.0000x reference)
#include <cuda_runtime.h>

// inputs: [128, 65536, 3] f32 interleaved (x,y,z)
// output: [128, 65536, 2] f32 interleaved (-phi*F, psi*F)
//
// phi = (clip(x,-1,1)+1)*pi/2 ; -phi*(180/pi) == -(clip(x,-1,1)+1)*90
// psi = acos(y/sqrt(y^2+z^2)), negated when z<0 ; psi*(180/pi)

static __device__ __forceinline__ void point_op(float x, float y, float z,
                                                float& o0, float& o1) {
    const float FACTOR = 57.295779513082323f;  // 180/pi
    float cx = fminf(fmaxf(x, -1.0f), 1.0f);
    o0 = -(cx + 1.0f) * 90.0f;
    float n = sqrtf(y * y + z * z);
    float psi = acosf(y / n);
    psi = (z < 0.0f) ? -psi : psi;
    o1 = psi * FACTOR;
}

__global__ void cil_kernel(const float4* __restrict__ in4,
                           float4* __restrict__ out4,
                           int n_quads) {
    int t = blockIdx.x * blockDim.x + threadIdx.x;
    if (t >= n_quads) return;

    // 4 points = 12 floats in = 3x float4 ; 8 floats out = 2x float4
    float4 a = in4[3 * t + 0];  // x0 y0 z0 x1
    float4 b = in4[3 * t + 1];  // y1 z1 x2 y2
    float4 c = in4[3 * t + 2];  // z2 x3 y3 z3

    float4 o0, o1;
    point_op(a.x, a.y, a.z, o0.x, o0.y);  // p0
    point_op(a.w, b.x, b.y, o0.z, o0.w);  // p1
    point_op(b.z, b.w, c.x, o1.x, o1.y);  // p2
    point_op(c.y, c.z, c.w, o1.z, o1.w);  // p3

    out4[2 * t + 0] = o0;
    out4[2 * t + 1] = o1;
}

extern "C" void kernel_launch(void* const* d_in, const int* in_sizes, int n_in,
                              void* d_out, int out_size) {
    const float4* in4 = (const float4*)d_in[0];
    float4* out4 = (float4*)d_out;

    int n_points = in_sizes[0] / 3;      // 8,388,608
    int n_quads = n_points / 4;          // 2,097,152 (exact: divisible)

    const int TPB = 256;
    int blocks = (n_quads + TPB - 1) / TPB;
    cil_kernel<<<blocks, TPB>>>(in4, out4, n_quads);
}